// round 15
// baseline (speedup 1.0000x reference)
#include <cuda_runtime.h>
#include <cstdint>

#define Bn 256
#define Tn 1024
#define Cn 256
#define Ln 128
#define NEP 64            // 64 epochs x 16 steps: t = 16e+1 .. 16e+16 (last guarded)
#define RROWS 64          // 4-epoch ring, slot = t & 63
#define NEGF (-1e30f)
#define EPSF (1e-7f)
#define NTH 128           // 4 warps
#define LN2F 0.6931471805599453f

// grid = 256 (one batch row per block), dynamic smem ~94KB, 2 blocks/SM.
// Roles (role = wid ^ ((blockIdx.x & 1) << 1) — spreads the 2 co-resident
// blocks' rec warps across different SMSPs):
//  role 0: recurrence. Lane l owns states 8l..8l+7, per-lane exponent E_l,
//          one shfl_up/step; reads PRE-GATHERED emissions (vg) — no ring
//          access, no bank conflicts, EPSF pre-added.
//  role 1: loader: cp.async prefetch 3 epochs ahead, wait_group 1.
//  roles 2,3: per-row denominator sums + blank capture for epoch e (8 rows
//          each, interleaved shfl trees) AND emission pre-gather for epoch
//          e+1 into vg[(e+1)&1] / vbp.
// State 256 excluded; reconstructed in epilogue (validated R4-R14).
// Per-LANE scaling is REQUIRED (global scaling failed in R2/R12).

__device__ __forceinline__ float ex2f(float x){ float r; asm("ex2.approx.ftz.f32 %0, %1;" : "=f"(r) : "f"(x)); return r; }
__device__ __forceinline__ float lg2f(float x){ float r; asm("lg2.approx.ftz.f32 %0, %1;" : "=f"(r) : "f"(x)); return r; }

extern __shared__ __align__(16) float smemf[];

#define OFF_RING  0                        // [RROWS][Cn] = 16384
#define OFF_SUMS  (OFF_RING + RROWS*Cn)    // [Tn]
#define OFF_VBH   (OFF_SUMS + Tn)          // [Tn]
#define OFF_HISTL (OFF_VBH + Tn)           // [Tn]
#define OFF_HISTE (OFF_HISTL + Tn)         // [NEP]
#define OFF_CSUM  (OFF_HISTE + NEP)        // [128]
#define OFF_COFF  (OFF_CSUM + 128)         // [128]
#define OFF_LABS  (OFF_COFF + 128)         // [Ln] ints
#define OFF_VG    (OFF_LABS + Ln)          // [2][16][128] = 4096 (16B aligned)
#define OFF_VBP   (OFF_VG + 4096)          // [2][16]
#define OFF_WREDA (OFF_VBP + 32)           // [4]
#define OFF_WREDB (OFF_WREDA + 4)
#define OFF_WREDC (OFF_WREDB + 4)
#define OFF_PTOT  (OFF_WREDC + 4)
#define OFF_F64   (OFF_PTOT + 1)
#define SMEM_FLOATS (OFF_F64 + 1)

__global__ __launch_bounds__(NTH, 2)
void ctc_kernel(const void* __restrict__ yt_raw,
                const float* __restrict__ yp,
                float* __restrict__ out)
{
    float* ring  = smemf + OFF_RING;     // ring[(t & 63)*Cn + c]
    float* sums  = smemf + OFF_SUMS;
    float* vbh   = smemf + OFF_VBH;
    float* histL = smemf + OFF_HISTL;
    float* histE = smemf + OFF_HISTE;
    float* csum  = smemf + OFF_CSUM;
    float* coff  = smemf + OFF_COFF;
    int*   labs  = (int*)(smemf + OFF_LABS);
    float* vg    = smemf + OFF_VG;       // vg[(buf*16 + jj)*128 + 4*lane]
    float* vbp   = smemf + OFF_VBP;      // vbp[buf*16 + jj]
    float* wredA = smemf + OFF_WREDA;
    float* wredB = smemf + OFF_WREDB;
    float* wredC = smemf + OFF_WREDC;
    float* PtotS = smemf + OFF_PTOT;
    int*   flag64 = (int*)(smemf + OFF_F64);

    const int b    = blockIdx.x;
    const int tid  = threadIdx.x;
    const int wid  = tid >> 5;
    const int lane = tid & 31;
    const int role = wid ^ ((b & 1) << 1);
    const float* rowbase = yp + (size_t)b * Tn * Cn;

    if (tid == 0) *flag64 = 1;

    // ---- prologue: loader loads rows 0..48 in 3 groups of ~16 rows ----
    if (role == 1) {
        #pragma unroll 1
        for (int grp = 0; grp < 3; ++grp) {
            const int lo = (grp == 0) ? 0 : 16 * grp + 1;
            const int hi = 16 * grp + 16;
            for (int rr = lo; rr <= hi; ++rr) {
                unsigned sa = (unsigned)__cvta_generic_to_shared(&ring[rr * Cn + lane * 8]);
                const float* g = rowbase + (size_t)rr * Cn + lane * 8;
                asm volatile("cp.async.cg.shared.global [%0], [%1], 16;\n" :: "r"(sa), "l"(g));
                asm volatile("cp.async.cg.shared.global [%0], [%1], 16;\n" :: "r"(sa + 16), "l"(g + 4));
            }
            asm volatile("cp.async.commit_group;\n");
        }
        asm volatile("cp.async.wait_group 1;\n");   // rows 0..32 resident
    }
    __syncthreads();

    // label dtype detect (int64 -> odd int32 words of first 128 pairs are 0)
    if (((const int*)yt_raw)[2 * tid + 1] != 0) *flag64 = 0;
    __syncthreads();
    const int f64 = *flag64;

    // stage labels through smem
    if (tid < Ln) {
        int v = f64 ? (int)((const long long*)yt_raw)[(size_t)b * Ln + tid]
                    : ((const int*)yt_raw)[(size_t)b * Ln + tid];
        labs[tid] = v & 255;
    }
    __syncthreads();

    // per-lane labels/skips for ALL warps (gatherers need vo too)
    int vo0, vo1, vo2, vo3;
    float sk0, sk1, sk2, sk3;
    {
        const int i0 = 4 * lane;
        vo0 = labs[i0]; vo1 = labs[i0+1]; vo2 = labs[i0+2]; vo3 = labs[i0+3];
        sk0 = (i0 >= 1 && vo0 != labs[i0-1]) ? 1.f : 0.f;
        sk1 = (vo1 != vo0) ? 1.f : 0.f;
        sk2 = (vo2 != vo1) ? 1.f : 0.f;
        sk3 = (vo3 != vo2) ? 1.f : 0.f;
    }

    // ---- init: t=0 alpha, row-0 denominator, prefill vg[0] (rows 1..16) ----
    float A0=0.f, A1=0.f, A2=0.f, A3=0.f, A4=0.f, A5=0.f, A6=0.f, A7=0.f;
    int E = 0;
    float pvScale = (lane == 0) ? 0.f : 1.f;
    if (role == 0) {
        if (lane == 0) {
            A0 = ring[Cn - 1] + EPSF;      // state 0 (blank), row 0 in slot 0
            A1 = ring[vo0] + EPSF;         // state 1 (label 0)
        }
    } else if (role >= 2) {
        const int rbase = (role == 2) ? 0 : 8;
        if (role == 2) {                   // row-0 denominator
            const float4* r4 = (const float4*)ring;
            float4 x = r4[lane], y = r4[lane + 32];
            float part = ((x.x + x.y) + (x.z + x.w)) + ((y.x + y.y) + (y.z + y.w));
            #pragma unroll
            for (int o = 16; o; o >>= 1) part += __shfl_xor_sync(0xffffffffu, part, o);
            if (lane == 0) sums[0] = part + (float)Cn * EPSF;
        }
        #pragma unroll
        for (int rr = 0; rr < 8; ++rr) {   // prefill vg[0]: rows t2 = 1+rbase+rr
            const int t2 = 1 + rbase + rr;
            const float* rg = &ring[(t2 & 63) * Cn];
            float4 w = { rg[vo0] + EPSF, rg[vo1] + EPSF, rg[vo2] + EPSF, rg[vo3] + EPSF };
            *(float4*)&vg[(rbase + rr) * 128 + 4 * lane] = w;
            if (lane == 0) vbp[rbase + rr] = rg[Cn - 1] + EPSF;
        }
    }
    __syncthreads();

    // ---- main loop: 64 epochs x 16 steps ----
    for (int e = 0; e < NEP; ++e) {
        if (role == 0) {
            if (e) {   // per-LANE exact pow2 renorm over the lane's 8 states
                const float M = fmaxf(fmaxf(fmaxf(A0, A1), fmaxf(A2, A3)),
                                      fmaxf(fmaxf(A4, A5), fmaxf(A6, A7)));
                int d = 0;
                if (M > 0.f) d = ((__float_as_int(M) >> 23) & 255) - 127;
                const float sc = __int_as_float((127 - d) << 23);   // exact 2^-d
                A0 *= sc; A1 *= sc; A2 *= sc; A3 *= sc;
                A4 *= sc; A5 *= sc; A6 *= sc; A7 *= sc;
                E += d;
                const int Ep = __shfl_up_sync(0xffffffffu, E, 1);
                if (lane > 0)
                    pvScale = ex2f(fminf((float)(Ep - E), 100.f));
            }
            if (lane == 31) histE[e] = (float)E;

            const int vbase = (e & 1) * 16;
            #pragma unroll
            for (int jj = 0; jj < 16; ++jj) {
                const int t = 16 * e + 1 + jj;      // warp-uniform
                if (t < Tn) {
                    const float4 vv = *(const float4*)&vg[(vbase + jj) * 128 + 4 * lane];
                    const float vb = vbp[vbase + jj];
                    const float pv = __shfl_up_sync(0xffffffffu, A7, 1) * pvScale;
                    A7 = fmaf(sk3, A5, A7 + A6) * vv.w;
                    A6 = (A6 + A5) * vb;
                    A5 = fmaf(sk2, A3, A5 + A4) * vv.z;
                    A4 = (A4 + A3) * vb;
                    A3 = fmaf(sk1, A1, A3 + A2) * vv.y;
                    A2 = (A2 + A1) * vb;
                    A1 = fmaf(sk0, pv, A1 + A0) * vv.x;
                    A0 = (A0 + pv) * vb;
                    if (lane == 31) histL[t] = A7;  // A255(t) at lane-31 frame
                }
            }
        }
        else if (role == 1) {
            // prefetch epoch e+3: rows 16e+49 .. 16e+64
            for (int rr = 0; rr < 16; ++rr) {
                const int rt = 16 * e + 49 + rr;
                if (rt < Tn) {
                    unsigned sa = (unsigned)__cvta_generic_to_shared(&ring[(rt & 63) * Cn + lane * 8]);
                    const float* g = rowbase + (size_t)rt * Cn + lane * 8;
                    asm volatile("cp.async.cg.shared.global [%0], [%1], 16;\n" :: "r"(sa), "l"(g));
                    asm volatile("cp.async.cg.shared.global [%0], [%1], 16;\n" :: "r"(sa + 16), "l"(g + 4));
                }
            }
            asm volatile("cp.async.commit_group;\n");
            asm volatile("cp.async.wait_group 1;\n");   // epoch e+2 rows resident
        }
        else {
            const int rbase = (role == 2) ? 0 : 8;
            // 1) denominator + vbh capture for epoch e rows (interleaved trees)
            float part[8];
            #pragma unroll
            for (int rr = 0; rr < 8; ++rr) {
                const int t = 16 * e + 1 + rbase + rr;
                if (t < Tn) {
                    const float4* r4 = (const float4*)&ring[(t & 63) * Cn];
                    float4 x = r4[lane], y = r4[lane + 32];
                    part[rr] = ((x.x + x.y) + (x.z + x.w)) + ((y.x + y.y) + (y.z + y.w));
                    if (lane == 31) vbh[t] = y.w;       // row[t][255] raw
                } else part[rr] = 0.f;
            }
            #pragma unroll
            for (int o = 16; o; o >>= 1) {
                #pragma unroll
                for (int rr = 0; rr < 8; ++rr)
                    part[rr] += __shfl_xor_sync(0xffffffffu, part[rr], o);
            }
            if (lane == 0) {
                #pragma unroll
                for (int rr = 0; rr < 8; ++rr) {
                    const int t = 16 * e + 1 + rbase + rr;
                    if (t < Tn) sums[t] = part[rr] + (float)Cn * EPSF;
                }
            }
            // 2) emission pre-gather for epoch e+1 rows into vg[(e+1)&1]
            const int nbase = ((e + 1) & 1) * 16;
            #pragma unroll
            for (int rr = 0; rr < 8; ++rr) {
                const int t2 = 16 * e + 17 + rbase + rr;
                if (t2 < Tn) {
                    const float* rg = &ring[(t2 & 63) * Cn];
                    float4 w = { rg[vo0] + EPSF, rg[vo1] + EPSF,
                                 rg[vo2] + EPSF, rg[vo3] + EPSF };
                    *(float4*)&vg[(nbase + rbase + rr) * 128 + 4 * lane] = w;
                    if (lane == 0) vbp[nbase + rbase + rr] = rg[Cn - 1] + EPSF;
                }
            }
        }
        __syncthreads();
    }

    // ==== epilogue: A256 reconstruction + D (proven structure; 128 threads) ====
    {
        const int base = 8 * tid;
        float acc = 0.f;
        #pragma unroll
        for (int j = 0; j < 8; ++j) {
            const int u = base + j;
            const float x = (u == 0) ? 0.f : lg2f(vbh[u] + EPSF);
            acc += x;
            vbh[u] = acc;                    // in-place within-chunk prefix
        }
        csum[tid] = acc;
    }
    __syncthreads();

    if (tid < 32) {     // exclusive scan of 128 chunk sums (4 per thread)
        const float c0 = csum[4*tid], c1 = csum[4*tid+1],
                    c2 = csum[4*tid+2], c3 = csum[4*tid+3];
        const float tot = ((c0 + c1) + (c2 + c3));
        float sc = tot;
        #pragma unroll
        for (int o = 1; o < 32; o <<= 1) {
            const float v = __shfl_up_sync(0xffffffffu, sc, o);
            if (tid >= o) sc += v;
        }
        const float ex = sc - tot;
        coff[4*tid]   = ex;
        coff[4*tid+1] = ex + c0;
        coff[4*tid+2] = ex + c0 + c1;
        coff[4*tid+3] = ex + c0 + c1 + c2;
        if (tid == 31) *PtotS = sc;
    }
    __syncthreads();

    const float Ptot = *PtotS;
    float lm = -3.0e38f;
    for (int u = tid; u < Tn - 1; u += NTH) {
        const float hl = (u == 0) ? 0.f : histL[u];
        float h = NEGF;
        if (u > 0 && hl > 0.f) h = histE[(u - 1) >> 4] + lg2f(hl);
        lm = fmaxf(lm, h + (Ptot - (coff[u >> 3] + vbh[u])));
    }
    float d2 = 0.f;
    #pragma unroll
    for (int j = 0; j < Tn / NTH; ++j) d2 += lg2f(sums[tid + NTH * j]);
    #pragma unroll
    for (int o = 16; o; o >>= 1) {
        lm = fmaxf(lm, __shfl_xor_sync(0xffffffffu, lm, o));
        d2 += __shfl_xor_sync(0xffffffffu, d2, o);
    }
    if (lane == 0) { wredA[wid] = lm; wredB[wid] = d2; }
    __syncthreads();

    const float M = fmaxf(fmaxf(wredA[0], wredA[1]), fmaxf(wredA[2], wredA[3]));

    float se = 0.f;
    for (int u = tid; u < Tn - 1; u += NTH) {
        const float hl = (u == 0) ? 0.f : histL[u];
        float h = NEGF;
        if (u > 0 && hl > 0.f) h = histE[(u - 1) >> 4] + lg2f(hl);
        se += ex2f(h + (Ptot - (coff[u >> 3] + vbh[u])) - M);
    }
    #pragma unroll
    for (int o = 16; o; o >>= 1) se += __shfl_xor_sync(0xffffffffu, se, o);
    if (lane == 0) wredC[wid] = se;
    __syncthreads();

    if (tid == 0) {
        float S = 0.f, D2 = 0.f;
        #pragma unroll
        for (int w = 0; w < 4; ++w) { S += wredC[w]; D2 += wredB[w]; }
        const float a256 = M + lg2f(S);                 // A256(T-1), base-2
        const float hf = histL[Tn - 1];
        const float x = (hf > 0.f) ? histE[NEP - 1] + lg2f(hf) : NEGF;  // A255(T-1)
        const float m2 = fmaxf(x, a256);
        const float lse2 = m2 + lg2f(ex2f(x - m2) + ex2f(a256 - m2));
        out[b] = LN2F * (D2 - lse2);
    }
}

extern "C" void kernel_launch(void* const* d_in, const int* in_sizes, int n_in,
                              void* d_out, int out_size)
{
    int iy = (in_sizes[0] == Bn * Ln) ? 0 : 1;
    const void*  yt = d_in[iy];
    const float* yp = (const float*)d_in[1 - iy];
    const size_t smem = SMEM_FLOATS * sizeof(float);
    cudaFuncSetAttribute(ctc_kernel, cudaFuncAttributeMaxDynamicSharedMemorySize, (int)smem);
    ctc_kernel<<<Bn, NTH, smem>>>(yt, yp, (float*)d_out);
}

// round 16
// speedup vs baseline: 1.2749x; 1.2749x over previous
#include <cuda_runtime.h>
#include <cstdint>

#define Bn 256
#define Tn 1024
#define Cn 256
#define Ln 128
#define NEP 64            // 64 epochs x 16 steps: t = 16e+1 .. 16e+16 (last guarded)
#define RROWS 64          // 4-epoch ring, slot = t & 63
#define NEGF (-1e30f)
#define EPSF (1e-7f)
#define NTH 192           // 6 warps
#define LN2F 0.6931471805599453f

// grid = 256 (one batch row per block), dynamic smem ~95KB, 2 blocks/SM.
// Roles (odd blocks: role = wid ^ 1 -> co-resident rec warps on SMSP0/SMSP1):
//  role 0: recurrence. Lane l owns states 8l..8l+7, per-lane exponent E_l
//          (REQUIRED: global scaling failed R2/R12), one shfl_up/step; reads
//          PRE-GATHERED emissions (vg) - conflict-free LDS.128, EPSF pre-added.
//  role 1: loader: cp.async prefetch 3 epochs ahead, wait_group 1.
//  roles 2-5: FOUR helper warps (R15's two were the critical path): each owns
//          4 rows of epoch-e denominator sums + blank capture AND 4 rows of
//          epoch-(e+1) emission pre-gather into vg[(e+1)&1] / vbp.
// State 256 excluded; reconstructed in epilogue (validated R4-R15).

__device__ __forceinline__ float ex2f(float x){ float r; asm("ex2.approx.ftz.f32 %0, %1;" : "=f"(r) : "f"(x)); return r; }
__device__ __forceinline__ float lg2f(float x){ float r; asm("lg2.approx.ftz.f32 %0, %1;" : "=f"(r) : "f"(x)); return r; }

extern __shared__ __align__(16) float smemf[];

#define OFF_RING  0                        // [RROWS][Cn] = 16384
#define OFF_SUMS  (OFF_RING + RROWS*Cn)    // [Tn]
#define OFF_VBH   (OFF_SUMS + Tn)          // [Tn]
#define OFF_HISTL (OFF_VBH + Tn)           // [Tn]
#define OFF_HISTE (OFF_HISTL + Tn)         // [NEP]
#define OFF_CSUM  (OFF_HISTE + NEP)        // [128]
#define OFF_COFF  (OFF_CSUM + 128)         // [128]
#define OFF_LABS  (OFF_COFF + 128)         // [Ln] ints
#define OFF_VG    (OFF_LABS + Ln)          // [2][16][128] = 4096
#define OFF_VBP   (OFF_VG + 4096)          // [2][16]
#define OFF_WREDA (OFF_VBP + 32)           // [6]
#define OFF_WREDB (OFF_WREDA + 6)          // [6]
#define OFF_WREDC (OFF_WREDB + 6)          // [6]
#define OFF_PTOT  (OFF_WREDC + 6)
#define OFF_F64   (OFF_PTOT + 1)
#define SMEM_FLOATS (OFF_F64 + 1)

__global__ __launch_bounds__(NTH, 2)
void ctc_kernel(const void* __restrict__ yt_raw,
                const float* __restrict__ yp,
                float* __restrict__ out)
{
    float* ring  = smemf + OFF_RING;     // ring[(t & 63)*Cn + c]
    float* sums  = smemf + OFF_SUMS;
    float* vbh   = smemf + OFF_VBH;
    float* histL = smemf + OFF_HISTL;
    float* histE = smemf + OFF_HISTE;
    float* csum  = smemf + OFF_CSUM;
    float* coff  = smemf + OFF_COFF;
    int*   labs  = (int*)(smemf + OFF_LABS);
    float* vg    = smemf + OFF_VG;       // vg[(buf*16 + jj)*128 + 4*lane]
    float* vbp   = smemf + OFF_VBP;      // vbp[buf*16 + jj]
    float* wredA = smemf + OFF_WREDA;
    float* wredB = smemf + OFF_WREDB;
    float* wredC = smemf + OFF_WREDC;
    float* PtotS = smemf + OFF_PTOT;
    int*   flag64 = (int*)(smemf + OFF_F64);

    const int b    = blockIdx.x;
    const int tid  = threadIdx.x;
    const int wid  = tid >> 5;
    const int lane = tid & 31;
    const int role = (b & 1) ? (wid ^ 1) : wid;
    const float* rowbase = yp + (size_t)b * Tn * Cn;

    if (tid == 0) *flag64 = 1;

    // ---- prologue: loader loads rows 0..48 in 3 groups ----
    if (role == 1) {
        #pragma unroll 1
        for (int grp = 0; grp < 3; ++grp) {
            const int lo = (grp == 0) ? 0 : 16 * grp + 1;
            const int hi = 16 * grp + 16;
            for (int rr = lo; rr <= hi; ++rr) {
                unsigned sa = (unsigned)__cvta_generic_to_shared(&ring[rr * Cn + lane * 8]);
                const float* g = rowbase + (size_t)rr * Cn + lane * 8;
                asm volatile("cp.async.cg.shared.global [%0], [%1], 16;\n" :: "r"(sa), "l"(g));
                asm volatile("cp.async.cg.shared.global [%0], [%1], 16;\n" :: "r"(sa + 16), "l"(g + 4));
            }
            asm volatile("cp.async.commit_group;\n");
        }
        asm volatile("cp.async.wait_group 1;\n");   // rows 0..32 resident
    }
    __syncthreads();

    // label dtype detect (int64 -> odd int32 words of first 128 pairs are 0)
    if (tid < 128) { if (((const int*)yt_raw)[2 * tid + 1] != 0) *flag64 = 0; }
    __syncthreads();
    const int f64 = *flag64;

    // stage labels through smem
    if (tid < Ln) {
        int v = f64 ? (int)((const long long*)yt_raw)[(size_t)b * Ln + tid]
                    : ((const int*)yt_raw)[(size_t)b * Ln + tid];
        labs[tid] = v & 255;
    }
    __syncthreads();

    // per-lane labels/skips for ALL warps (helpers need vo too)
    int vo0, vo1, vo2, vo3;
    float sk0, sk1, sk2, sk3;
    {
        const int i0 = 4 * lane;
        vo0 = labs[i0]; vo1 = labs[i0+1]; vo2 = labs[i0+2]; vo3 = labs[i0+3];
        sk0 = (i0 >= 1 && vo0 != labs[i0-1]) ? 1.f : 0.f;
        sk1 = (vo1 != vo0) ? 1.f : 0.f;
        sk2 = (vo2 != vo1) ? 1.f : 0.f;
        sk3 = (vo3 != vo2) ? 1.f : 0.f;
    }

    // ---- init: t=0 alpha, row-0 denominator, prefill vg[0] (rows 1..16) ----
    float A0=0.f, A1=0.f, A2=0.f, A3=0.f, A4=0.f, A5=0.f, A6=0.f, A7=0.f;
    int E = 0;
    float pvScale = (lane == 0) ? 0.f : 1.f;
    if (role == 0) {
        if (lane == 0) {
            A0 = ring[Cn - 1] + EPSF;      // state 0 (blank), row 0 in slot 0
            A1 = ring[vo0] + EPSF;         // state 1 (label 0)
        }
    } else if (role >= 2) {
        const int rbase = (role - 2) * 4;  // 0,4,8,12
        if (role == 2) {                   // row-0 denominator
            const float4* r4 = (const float4*)ring;
            float4 x = r4[lane], y = r4[lane + 32];
            float part = ((x.x + x.y) + (x.z + x.w)) + ((y.x + y.y) + (y.z + y.w));
            #pragma unroll
            for (int o = 16; o; o >>= 1) part += __shfl_xor_sync(0xffffffffu, part, o);
            if (lane == 0) sums[0] = part + (float)Cn * EPSF;
        }
        #pragma unroll
        for (int rr = 0; rr < 4; ++rr) {   // prefill vg[0]: rows t2 = 1+rbase+rr
            const int t2 = 1 + rbase + rr;
            const float* rg = &ring[(t2 & 63) * Cn];
            float4 w = { rg[vo0] + EPSF, rg[vo1] + EPSF, rg[vo2] + EPSF, rg[vo3] + EPSF };
            *(float4*)&vg[(rbase + rr) * 128 + 4 * lane] = w;
            if (lane == 0) vbp[rbase + rr] = rg[Cn - 1] + EPSF;
        }
    }
    __syncthreads();

    // ---- main loop: 64 epochs x 16 steps ----
    for (int e = 0; e < NEP; ++e) {
        if (role == 0) {
            if (e) {   // per-LANE exact pow2 renorm over the lane's 8 states
                const float M = fmaxf(fmaxf(fmaxf(A0, A1), fmaxf(A2, A3)),
                                      fmaxf(fmaxf(A4, A5), fmaxf(A6, A7)));
                int d = 0;
                if (M > 0.f) d = ((__float_as_int(M) >> 23) & 255) - 127;
                const float sc = __int_as_float((127 - d) << 23);   // exact 2^-d
                A0 *= sc; A1 *= sc; A2 *= sc; A3 *= sc;
                A4 *= sc; A5 *= sc; A6 *= sc; A7 *= sc;
                E += d;
                const int Ep = __shfl_up_sync(0xffffffffu, E, 1);
                if (lane > 0)
                    pvScale = ex2f(fminf((float)(Ep - E), 100.f));
            }
            if (lane == 31) histE[e] = (float)E;

            const int vbase = (e & 1) * 16;
            #pragma unroll
            for (int jj = 0; jj < 16; ++jj) {
                const int t = 16 * e + 1 + jj;      // warp-uniform
                if (t < Tn) {
                    const float4 vv = *(const float4*)&vg[(vbase + jj) * 128 + 4 * lane];
                    const float vb = vbp[vbase + jj];
                    const float pv = __shfl_up_sync(0xffffffffu, A7, 1) * pvScale;
                    A7 = fmaf(sk3, A5, A7 + A6) * vv.w;
                    A6 = (A6 + A5) * vb;
                    A5 = fmaf(sk2, A3, A5 + A4) * vv.z;
                    A4 = (A4 + A3) * vb;
                    A3 = fmaf(sk1, A1, A3 + A2) * vv.y;
                    A2 = (A2 + A1) * vb;
                    A1 = fmaf(sk0, pv, A1 + A0) * vv.x;
                    A0 = (A0 + pv) * vb;
                    if (lane == 31) histL[t] = A7;  // A255(t) at lane-31 frame
                }
            }
        }
        else if (role == 1) {
            // prefetch epoch e+3: rows 16e+49 .. 16e+64
            for (int rr = 0; rr < 16; ++rr) {
                const int rt = 16 * e + 49 + rr;
                if (rt < Tn) {
                    unsigned sa = (unsigned)__cvta_generic_to_shared(&ring[(rt & 63) * Cn + lane * 8]);
                    const float* g = rowbase + (size_t)rt * Cn + lane * 8;
                    asm volatile("cp.async.cg.shared.global [%0], [%1], 16;\n" :: "r"(sa), "l"(g));
                    asm volatile("cp.async.cg.shared.global [%0], [%1], 16;\n" :: "r"(sa + 16), "l"(g + 4));
                }
            }
            asm volatile("cp.async.commit_group;\n");
            asm volatile("cp.async.wait_group 1;\n");   // epoch e+2 rows resident
        }
        else {
            const int rbase = (role - 2) * 4;  // 0,4,8,12
            // 1) denominator + vbh capture for 4 epoch-e rows (interleaved trees)
            float part[4];
            #pragma unroll
            for (int rr = 0; rr < 4; ++rr) {
                const int t = 16 * e + 1 + rbase + rr;
                if (t < Tn) {
                    const float4* r4 = (const float4*)&ring[(t & 63) * Cn];
                    float4 x = r4[lane], y = r4[lane + 32];
                    part[rr] = ((x.x + x.y) + (x.z + x.w)) + ((y.x + y.y) + (y.z + y.w));
                    if (lane == 31) vbh[t] = y.w;       // row[t][255] raw
                } else part[rr] = 0.f;
            }
            #pragma unroll
            for (int o = 16; o; o >>= 1) {
                #pragma unroll
                for (int rr = 0; rr < 4; ++rr)
                    part[rr] += __shfl_xor_sync(0xffffffffu, part[rr], o);
            }
            if (lane == 0) {
                #pragma unroll
                for (int rr = 0; rr < 4; ++rr) {
                    const int t = 16 * e + 1 + rbase + rr;
                    if (t < Tn) sums[t] = part[rr] + (float)Cn * EPSF;
                }
            }
            // 2) emission pre-gather for 4 epoch-(e+1) rows into vg[(e+1)&1]
            const int nbase = ((e + 1) & 1) * 16;
            #pragma unroll
            for (int rr = 0; rr < 4; ++rr) {
                const int t2 = 16 * e + 17 + rbase + rr;
                if (t2 < Tn) {
                    const float* rg = &ring[(t2 & 63) * Cn];
                    float4 w = { rg[vo0] + EPSF, rg[vo1] + EPSF,
                                 rg[vo2] + EPSF, rg[vo3] + EPSF };
                    *(float4*)&vg[(nbase + rbase + rr) * 128 + 4 * lane] = w;
                    if (lane == 0) vbp[nbase + rbase + rr] = rg[Cn - 1] + EPSF;
                }
            }
        }
        __syncthreads();
    }

    // ==== epilogue: A256 reconstruction + D (proven structure) ====
    if (tid < 128) {
        const int base = 8 * tid;
        float acc = 0.f;
        #pragma unroll
        for (int j = 0; j < 8; ++j) {
            const int u = base + j;
            const float x = (u == 0) ? 0.f : lg2f(vbh[u] + EPSF);
            acc += x;
            vbh[u] = acc;                    // in-place within-chunk prefix
        }
        csum[tid] = acc;
    }
    __syncthreads();

    if (tid < 32) {     // exclusive scan of 128 chunk sums (4 per thread)
        const float c0 = csum[4*tid], c1 = csum[4*tid+1],
                    c2 = csum[4*tid+2], c3 = csum[4*tid+3];
        const float tot = ((c0 + c1) + (c2 + c3));
        float sc = tot;
        #pragma unroll
        for (int o = 1; o < 32; o <<= 1) {
            const float v = __shfl_up_sync(0xffffffffu, sc, o);
            if (tid >= o) sc += v;
        }
        const float ex = sc - tot;
        coff[4*tid]   = ex;
        coff[4*tid+1] = ex + c0;
        coff[4*tid+2] = ex + c0 + c1;
        coff[4*tid+3] = ex + c0 + c1 + c2;
        if (tid == 31) *PtotS = sc;
    }
    __syncthreads();

    const float Ptot = *PtotS;
    float lm = -3.0e38f;
    for (int u = tid; u < Tn - 1; u += NTH) {
        const float hl = (u == 0) ? 0.f : histL[u];
        float h = NEGF;
        if (u > 0 && hl > 0.f) h = histE[(u - 1) >> 4] + lg2f(hl);
        lm = fmaxf(lm, h + (Ptot - (coff[u >> 3] + vbh[u])));
    }
    float d2 = 0.f;
    for (int t2 = tid; t2 < Tn; t2 += NTH) d2 += lg2f(sums[t2]);
    #pragma unroll
    for (int o = 16; o; o >>= 1) {
        lm = fmaxf(lm, __shfl_xor_sync(0xffffffffu, lm, o));
        d2 += __shfl_xor_sync(0xffffffffu, d2, o);
    }
    if (lane == 0) { wredA[wid] = lm; wredB[wid] = d2; }
    __syncthreads();

    float M = wredA[0];
    #pragma unroll
    for (int w = 1; w < 6; ++w) M = fmaxf(M, wredA[w]);

    float se = 0.f;
    for (int u = tid; u < Tn - 1; u += NTH) {
        const float hl = (u == 0) ? 0.f : histL[u];
        float h = NEGF;
        if (u > 0 && hl > 0.f) h = histE[(u - 1) >> 4] + lg2f(hl);
        se += ex2f(h + (Ptot - (coff[u >> 3] + vbh[u])) - M);
    }
    #pragma unroll
    for (int o = 16; o; o >>= 1) se += __shfl_xor_sync(0xffffffffu, se, o);
    if (lane == 0) wredC[wid] = se;
    __syncthreads();

    if (tid == 0) {
        float S = 0.f, D2 = 0.f;
        #pragma unroll
        for (int w = 0; w < 6; ++w) { S += wredC[w]; D2 += wredB[w]; }
        const float a256 = M + lg2f(S);                 // A256(T-1), base-2
        const float hf = histL[Tn - 1];
        const float x = (hf > 0.f) ? histE[NEP - 1] + lg2f(hf) : NEGF;  // A255(T-1)
        const float m2 = fmaxf(x, a256);
        const float lse2 = m2 + lg2f(ex2f(x - m2) + ex2f(a256 - m2));
        out[b] = LN2F * (D2 - lse2);
    }
}

extern "C" void kernel_launch(void* const* d_in, const int* in_sizes, int n_in,
                              void* d_out, int out_size)
{
    int iy = (in_sizes[0] == Bn * Ln) ? 0 : 1;
    const void*  yt = d_in[iy];
    const float* yp = (const float*)d_in[1 - iy];
    const size_t smem = SMEM_FLOATS * sizeof(float);
    cudaFuncSetAttribute(ctc_kernel, cudaFuncAttributeMaxDynamicSharedMemorySize, (int)smem);
    ctc_kernel<<<Bn, NTH, smem>>>(yt, yp, (float*)d_out);
}

// round 17
// speedup vs baseline: 1.2754x; 1.0004x over previous
#include <cuda_runtime.h>
#include <cstdint>

#define Bn 256
#define Tn 1024
#define Cn 256
#define Ln 128
#define NEP 64            // 64 epochs x 16 steps: t = 16e+1 .. 16e+16 (last guarded)
#define RROWS 64          // 4-epoch ring, slot = t & 63
#define NEGF (-1e30f)
#define EPSF (1e-7f)
#define NTH 256           // 8 warps
#define LN2F 0.6931471805599453f

// grid = 256 (one batch row per block), dynamic smem ~95KB, 2 blocks/SM.
// Roles (odd blocks: role = wid ^ 2 -> the two co-resident rec warps land on
// SMSP0 vs SMSP2, loaders on SMSP1 vs SMSP3):
//  role 0: recurrence. Lane l owns states 8l..8l+7, per-lane exponent E_l
//          (REQUIRED: global scaling failed R2/R12), one shfl_up/step; reads
//          PRE-GATHERED emissions (vg) - conflict-free LDS.128, EPSF pre-added.
//  role 1: loader: cp.async prefetch 3 epochs ahead, wait_group 1.
//  roles 2-7: SIX helper warps (R16 had 4; helpers were the critical path):
//          each owns 2-3 rows of epoch-e denominator sums + blank capture AND
//          2-3 rows of epoch-(e+1) emission pre-gather into vg[(e+1)&1]/vbp.
// State 256 excluded; reconstructed in epilogue (validated R4-R16).

__device__ __forceinline__ float ex2f(float x){ float r; asm("ex2.approx.ftz.f32 %0, %1;" : "=f"(r) : "f"(x)); return r; }
__device__ __forceinline__ float lg2f(float x){ float r; asm("lg2.approx.ftz.f32 %0, %1;" : "=f"(r) : "f"(x)); return r; }

extern __shared__ __align__(16) float smemf[];

#define OFF_RING  0                        // [RROWS][Cn] = 16384
#define OFF_SUMS  (OFF_RING + RROWS*Cn)    // [Tn]
#define OFF_VBH   (OFF_SUMS + Tn)          // [Tn]
#define OFF_HISTL (OFF_VBH + Tn)           // [Tn]
#define OFF_HISTE (OFF_HISTL + Tn)         // [NEP]
#define OFF_CSUM  (OFF_HISTE + NEP)        // [128]
#define OFF_COFF  (OFF_CSUM + 128)         // [128]
#define OFF_LABS  (OFF_COFF + 128)         // [Ln] ints
#define OFF_VG    (OFF_LABS + Ln)          // [2][16][128] = 4096
#define OFF_VBP   (OFF_VG + 4096)          // [2][16]
#define OFF_WREDA (OFF_VBP + 32)           // [8]
#define OFF_WREDB (OFF_WREDA + 8)          // [8]
#define OFF_WREDC (OFF_WREDB + 8)          // [8]
#define OFF_PTOT  (OFF_WREDC + 8)
#define OFF_F64   (OFF_PTOT + 1)
#define SMEM_FLOATS (OFF_F64 + 1)

__global__ __launch_bounds__(NTH, 2)
void ctc_kernel(const void* __restrict__ yt_raw,
                const float* __restrict__ yp,
                float* __restrict__ out)
{
    float* ring  = smemf + OFF_RING;     // ring[(t & 63)*Cn + c]
    float* sums  = smemf + OFF_SUMS;
    float* vbh   = smemf + OFF_VBH;
    float* histL = smemf + OFF_HISTL;
    float* histE = smemf + OFF_HISTE;
    float* csum  = smemf + OFF_CSUM;
    float* coff  = smemf + OFF_COFF;
    int*   labs  = (int*)(smemf + OFF_LABS);
    float* vg    = smemf + OFF_VG;       // vg[(buf*16 + jj)*128 + 4*lane]
    float* vbp   = smemf + OFF_VBP;      // vbp[buf*16 + jj]
    float* wredA = smemf + OFF_WREDA;
    float* wredB = smemf + OFF_WREDB;
    float* wredC = smemf + OFF_WREDC;
    float* PtotS = smemf + OFF_PTOT;
    int*   flag64 = (int*)(smemf + OFF_F64);

    const int b    = blockIdx.x;
    const int tid  = threadIdx.x;
    const int wid  = tid >> 5;
    const int lane = tid & 31;
    const int role = (b & 1) ? (wid ^ 2) : wid;
    const float* rowbase = yp + (size_t)b * Tn * Cn;

    if (tid == 0) *flag64 = 1;

    // ---- prologue: loader loads rows 0..48 in 3 groups ----
    if (role == 1) {
        #pragma unroll 1
        for (int grp = 0; grp < 3; ++grp) {
            const int lo = (grp == 0) ? 0 : 16 * grp + 1;
            const int hi = 16 * grp + 16;
            for (int rr = lo; rr <= hi; ++rr) {
                unsigned sa = (unsigned)__cvta_generic_to_shared(&ring[rr * Cn + lane * 8]);
                const float* g = rowbase + (size_t)rr * Cn + lane * 8;
                asm volatile("cp.async.cg.shared.global [%0], [%1], 16;\n" :: "r"(sa), "l"(g));
                asm volatile("cp.async.cg.shared.global [%0], [%1], 16;\n" :: "r"(sa + 16), "l"(g + 4));
            }
            asm volatile("cp.async.commit_group;\n");
        }
        asm volatile("cp.async.wait_group 1;\n");   // rows 0..32 resident
    }
    __syncthreads();

    // label dtype detect (int64 -> odd int32 words of first 128 pairs are 0)
    if (tid < 128) { if (((const int*)yt_raw)[2 * tid + 1] != 0) *flag64 = 0; }
    __syncthreads();
    const int f64 = *flag64;

    // stage labels through smem
    if (tid < Ln) {
        int v = f64 ? (int)((const long long*)yt_raw)[(size_t)b * Ln + tid]
                    : ((const int*)yt_raw)[(size_t)b * Ln + tid];
        labs[tid] = v & 255;
    }
    __syncthreads();

    // per-lane labels/skips for ALL warps (helpers need vo too)
    int vo0, vo1, vo2, vo3;
    float sk0, sk1, sk2, sk3;
    {
        const int i0 = 4 * lane;
        vo0 = labs[i0]; vo1 = labs[i0+1]; vo2 = labs[i0+2]; vo3 = labs[i0+3];
        sk0 = (i0 >= 1 && vo0 != labs[i0-1]) ? 1.f : 0.f;
        sk1 = (vo1 != vo0) ? 1.f : 0.f;
        sk2 = (vo2 != vo1) ? 1.f : 0.f;
        sk3 = (vo3 != vo2) ? 1.f : 0.f;
    }

    // helper row ranges: helpers 0..3 -> 3 rows at 3h; helpers 4,5 -> 2 rows at 12+2(h-4)
    const int hh    = role - 2;
    const int rbase = (hh < 4) ? 3 * hh : 12 + 2 * (hh - 4);
    const int rcnt  = (hh < 4) ? 3 : 2;

    // ---- init: t=0 alpha, row-0 denominator, prefill vg[0] (rows 1..16) ----
    float A0=0.f, A1=0.f, A2=0.f, A3=0.f, A4=0.f, A5=0.f, A6=0.f, A7=0.f;
    int E = 0;
    float pvScale = (lane == 0) ? 0.f : 1.f;
    if (role == 0) {
        if (lane == 0) {
            A0 = ring[Cn - 1] + EPSF;      // state 0 (blank), row 0 in slot 0
            A1 = ring[vo0] + EPSF;         // state 1 (label 0)
        }
    } else if (role >= 2) {
        if (role == 2) {                   // row-0 denominator
            const float4* r4 = (const float4*)ring;
            float4 x = r4[lane], y = r4[lane + 32];
            float part = ((x.x + x.y) + (x.z + x.w)) + ((y.x + y.y) + (y.z + y.w));
            #pragma unroll
            for (int o = 16; o; o >>= 1) part += __shfl_xor_sync(0xffffffffu, part, o);
            if (lane == 0) sums[0] = part + (float)Cn * EPSF;
        }
        #pragma unroll
        for (int rr = 0; rr < 3; ++rr) {   // prefill vg[0]: rows t2 = 1+rbase+rr
            if (rr < rcnt) {
                const int t2 = 1 + rbase + rr;
                const float* rg = &ring[(t2 & 63) * Cn];
                float4 w = { rg[vo0] + EPSF, rg[vo1] + EPSF, rg[vo2] + EPSF, rg[vo3] + EPSF };
                *(float4*)&vg[(rbase + rr) * 128 + 4 * lane] = w;
                if (lane == 0) vbp[rbase + rr] = rg[Cn - 1] + EPSF;
            }
        }
    }
    __syncthreads();

    // ---- main loop: 64 epochs x 16 steps ----
    for (int e = 0; e < NEP; ++e) {
        if (role == 0) {
            if (e) {   // per-LANE exact pow2 renorm over the lane's 8 states
                const float M = fmaxf(fmaxf(fmaxf(A0, A1), fmaxf(A2, A3)),
                                      fmaxf(fmaxf(A4, A5), fmaxf(A6, A7)));
                int d = 0;
                if (M > 0.f) d = ((__float_as_int(M) >> 23) & 255) - 127;
                const float sc = __int_as_float((127 - d) << 23);   // exact 2^-d
                A0 *= sc; A1 *= sc; A2 *= sc; A3 *= sc;
                A4 *= sc; A5 *= sc; A6 *= sc; A7 *= sc;
                E += d;
                const int Ep = __shfl_up_sync(0xffffffffu, E, 1);
                if (lane > 0)
                    pvScale = ex2f(fminf((float)(Ep - E), 100.f));
            }
            if (lane == 31) histE[e] = (float)E;

            const int vbase = (e & 1) * 16;
            #pragma unroll
            for (int jj = 0; jj < 16; ++jj) {
                const int t = 16 * e + 1 + jj;      // warp-uniform
                if (t < Tn) {
                    const float4 vv = *(const float4*)&vg[(vbase + jj) * 128 + 4 * lane];
                    const float vb = vbp[vbase + jj];
                    const float pv = __shfl_up_sync(0xffffffffu, A7, 1) * pvScale;
                    A7 = fmaf(sk3, A5, A7 + A6) * vv.w;
                    A6 = (A6 + A5) * vb;
                    A5 = fmaf(sk2, A3, A5 + A4) * vv.z;
                    A4 = (A4 + A3) * vb;
                    A3 = fmaf(sk1, A1, A3 + A2) * vv.y;
                    A2 = (A2 + A1) * vb;
                    A1 = fmaf(sk0, pv, A1 + A0) * vv.x;
                    A0 = (A0 + pv) * vb;
                    if (lane == 31) histL[t] = A7;  // A255(t) at lane-31 frame
                }
            }
        }
        else if (role == 1) {
            // prefetch epoch e+3: rows 16e+49 .. 16e+64
            for (int rr = 0; rr < 16; ++rr) {
                const int rt = 16 * e + 49 + rr;
                if (rt < Tn) {
                    unsigned sa = (unsigned)__cvta_generic_to_shared(&ring[(rt & 63) * Cn + lane * 8]);
                    const float* g = rowbase + (size_t)rt * Cn + lane * 8;
                    asm volatile("cp.async.cg.shared.global [%0], [%1], 16;\n" :: "r"(sa), "l"(g));
                    asm volatile("cp.async.cg.shared.global [%0], [%1], 16;\n" :: "r"(sa + 16), "l"(g + 4));
                }
            }
            asm volatile("cp.async.commit_group;\n");
            asm volatile("cp.async.wait_group 1;\n");   // epoch e+2 rows resident
        }
        else {
            // 1) denominator + vbh capture for this helper's epoch-e rows
            float part[3];
            #pragma unroll
            for (int rr = 0; rr < 3; ++rr) {
                part[rr] = 0.f;
                if (rr < rcnt) {
                    const int t = 16 * e + 1 + rbase + rr;
                    if (t < Tn) {
                        const float4* r4 = (const float4*)&ring[(t & 63) * Cn];
                        float4 x = r4[lane], y = r4[lane + 32];
                        part[rr] = ((x.x + x.y) + (x.z + x.w)) + ((y.x + y.y) + (y.z + y.w));
                        if (lane == 31) vbh[t] = y.w;   // row[t][255] raw
                    }
                }
            }
            #pragma unroll
            for (int o = 16; o; o >>= 1) {
                #pragma unroll
                for (int rr = 0; rr < 3; ++rr)
                    part[rr] += __shfl_xor_sync(0xffffffffu, part[rr], o);
            }
            if (lane == 0) {
                #pragma unroll
                for (int rr = 0; rr < 3; ++rr) {
                    if (rr < rcnt) {
                        const int t = 16 * e + 1 + rbase + rr;
                        if (t < Tn) sums[t] = part[rr] + (float)Cn * EPSF;
                    }
                }
            }
            // 2) emission pre-gather for this helper's epoch-(e+1) rows
            const int nbase = ((e + 1) & 1) * 16;
            #pragma unroll
            for (int rr = 0; rr < 3; ++rr) {
                if (rr < rcnt) {
                    const int t2 = 16 * e + 17 + rbase + rr;
                    if (t2 < Tn) {
                        const float* rg = &ring[(t2 & 63) * Cn];
                        float4 w = { rg[vo0] + EPSF, rg[vo1] + EPSF,
                                     rg[vo2] + EPSF, rg[vo3] + EPSF };
                        *(float4*)&vg[(nbase + rbase + rr) * 128 + 4 * lane] = w;
                        if (lane == 0) vbp[nbase + rbase + rr] = rg[Cn - 1] + EPSF;
                    }
                }
            }
        }
        __syncthreads();
    }

    // ==== epilogue: A256 reconstruction + D (proven structure) ====
    if (tid < 128) {
        const int base = 8 * tid;
        float acc = 0.f;
        #pragma unroll
        for (int j = 0; j < 8; ++j) {
            const int u = base + j;
            const float x = (u == 0) ? 0.f : lg2f(vbh[u] + EPSF);
            acc += x;
            vbh[u] = acc;                    // in-place within-chunk prefix
        }
        csum[tid] = acc;
    }
    __syncthreads();

    if (tid < 32) {     // exclusive scan of 128 chunk sums (4 per thread)
        const float c0 = csum[4*tid], c1 = csum[4*tid+1],
                    c2 = csum[4*tid+2], c3 = csum[4*tid+3];
        const float tot = ((c0 + c1) + (c2 + c3));
        float sc = tot;
        #pragma unroll
        for (int o = 1; o < 32; o <<= 1) {
            const float v = __shfl_up_sync(0xffffffffu, sc, o);
            if (tid >= o) sc += v;
        }
        const float ex = sc - tot;
        coff[4*tid]   = ex;
        coff[4*tid+1] = ex + c0;
        coff[4*tid+2] = ex + c0 + c1;
        coff[4*tid+3] = ex + c0 + c1 + c2;
        if (tid == 31) *PtotS = sc;
    }
    __syncthreads();

    const float Ptot = *PtotS;
    float lm = -3.0e38f;
    for (int u = tid; u < Tn - 1; u += NTH) {
        const float hl = (u == 0) ? 0.f : histL[u];
        float h = NEGF;
        if (u > 0 && hl > 0.f) h = histE[(u - 1) >> 4] + lg2f(hl);
        lm = fmaxf(lm, h + (Ptot - (coff[u >> 3] + vbh[u])));
    }
    float d2 = 0.f;
    #pragma unroll
    for (int j = 0; j < Tn / NTH; ++j) d2 += lg2f(sums[tid + NTH * j]);
    #pragma unroll
    for (int o = 16; o; o >>= 1) {
        lm = fmaxf(lm, __shfl_xor_sync(0xffffffffu, lm, o));
        d2 += __shfl_xor_sync(0xffffffffu, d2, o);
    }
    if (lane == 0) { wredA[wid] = lm; wredB[wid] = d2; }
    __syncthreads();

    float M = wredA[0];
    #pragma unroll
    for (int w = 1; w < 8; ++w) M = fmaxf(M, wredA[w]);

    float se = 0.f;
    for (int u = tid; u < Tn - 1; u += NTH) {
        const float hl = (u == 0) ? 0.f : histL[u];
        float h = NEGF;
        if (u > 0 && hl > 0.f) h = histE[(u - 1) >> 4] + lg2f(hl);
        se += ex2f(h + (Ptot - (coff[u >> 3] + vbh[u])) - M);
    }
    #pragma unroll
    for (int o = 16; o; o >>= 1) se += __shfl_xor_sync(0xffffffffu, se, o);
    if (lane == 0) wredC[wid] = se;
    __syncthreads();

    if (tid == 0) {
        float S = 0.f, D2 = 0.f;
        #pragma unroll
        for (int w = 0; w < 8; ++w) { S += wredC[w]; D2 += wredB[w]; }
        const float a256 = M + lg2f(S);                 // A256(T-1), base-2
        const float hf = histL[Tn - 1];
        const float x = (hf > 0.f) ? histE[NEP - 1] + lg2f(hf) : NEGF;  // A255(T-1)
        const float m2 = fmaxf(x, a256);
        const float lse2 = m2 + lg2f(ex2f(x - m2) + ex2f(a256 - m2));
        out[b] = LN2F * (D2 - lse2);
    }
}

extern "C" void kernel_launch(void* const* d_in, const int* in_sizes, int n_in,
                              void* d_out, int out_size)
{
    int iy = (in_sizes[0] == Bn * Ln) ? 0 : 1;
    const void*  yt = d_in[iy];
    const float* yp = (const float*)d_in[1 - iy];
    const size_t smem = SMEM_FLOATS * sizeof(float);
    cudaFuncSetAttribute(ctc_kernel, cudaFuncAttributeMaxDynamicSharedMemorySize, (int)smem);
    ctc_kernel<<<Bn, NTH, smem>>>(yt, yp, (float*)d_out);
}